// round 11
// baseline (speedup 1.0000x reference)
#include <cuda_runtime.h>

#define N_VERTS 53215
#define EXP_DIM 29
#define SHP_DIM 199
#define SHP3    (3 * SHP_DIM)   // 597
#define EXP3    (3 * EXP_DIM)   // 87

#define NTHREADS 256
#define WARPS_PER_BLOCK (NTHREADS / 32)

// ---------------------------------------------------------------------------
// Consolidated kernel (best measured ingredients of R2/R7/R10):
//  * warp-per-vertex, 6652 blocks x 256 thr (R2 geometry — best kernel time)
//  * plain LDG stream (R2; .cs variants measured marginally slower)
//  * alphas PRE-EXPANDED in smem: s_A[j] = alpha[j mod dim] for the full
//    597/87-float row group -> phase 2 is one LDS + one FFMA per element,
//    zero index arithmetic; routing compares only on straddle passes 6 & 12.
//  * __shfl_xor butterfly reduction -> all lanes hold sums; lanes 0..2 each
//    compute one output component (parallel epilogue instead of serial lane0).
//
// The kernel is at the HBM read wall (~5.3 TB/s for this 146MB touch-once
// stream); this round minimizes everything else.
//
// Transform (derived from _transform_matrix(pose, 450)):
//   s  = p3 + p7 + p11
//   ox = ( s*(p0x + p1y + p2z)  + p3)        * (224/450)
//   oy = (-s*(p4x + p5y + p6z)  - p7 + 450)  * (224/450)
//   oz =   s*(p8x + p9y + p10z)
// ---------------------------------------------------------------------------
__global__ void __launch_bounds__(NTHREADS, 6)
pca_final_kernel(const float* __restrict__ pose,
                 const float* __restrict__ a_exp,
                 const float* __restrict__ a_shp,
                 const float* __restrict__ u,
                 const float* __restrict__ w_exp,
                 const float* __restrict__ w_shp,
                 float* __restrict__ out)
{
    __shared__ float s_A[SHP3];   // expanded shp alphas: s_A[j] = a_shp[j % 199]
    __shared__ float s_E[EXP3];   // expanded exp alphas: s_E[j] = a_exp[j % 29]

    const int t = threadIdx.x;
    for (int j = t; j < SHP3; j += NTHREADS) {
        int col;
        if (j < SHP_DIM)          col = j;
        else if (j < 2 * SHP_DIM) col = j - SHP_DIM;
        else                      col = j - 2 * SHP_DIM;
        s_A[j] = a_shp[col];
    }
    if (t < EXP3) {
        int col;
        if (t < EXP_DIM)          col = t;
        else if (t < 2 * EXP_DIM) col = t - EXP_DIM;
        else                      col = t - 2 * EXP_DIM;
        s_E[t] = a_exp[col];
    }
    __syncthreads();

    const int warp = (blockIdx.x * blockDim.x + t) >> 5;
    const int lane = t & 31;
    if (warp >= N_VERTS) return;

    const float* __restrict__ ws = w_shp + (size_t)warp * SHP3;
    const float* __restrict__ we = w_exp + (size_t)warp * EXP3;

    float a0 = 0.f, a1 = 0.f, a2 = 0.f;

    // ---- SHP: 19 coalesced passes; only passes 6, 12, 18 need runtime tests ----
    #pragma unroll
    for (int i = 0; i < 19; i++) {
        const int j = i * 32 + lane;
        // pass-level routing constant-folds except straddle passes
        if (i < 6) {
            a0 += ws[j] * s_A[j];
        } else if (i == 6) {                       // straddles j = 199
            const float p = ws[j] * s_A[j];
            if (j < SHP_DIM) a0 += p; else a1 += p;
        } else if (i < 12) {
            a1 += ws[j] * s_A[j];
        } else if (i == 12) {                      // straddles j = 398
            const float p = ws[j] * s_A[j];
            if (j < 2 * SHP_DIM) a1 += p; else a2 += p;
        } else if (i < 18) {
            a2 += ws[j] * s_A[j];
        } else {                                   // tail pass, j < 597
            if (j < SHP3) a2 += ws[j] * s_A[j];
        }
    }

    // ---- EXP: 3 passes, each straddles a boundary ----
    #pragma unroll
    for (int i = 0; i < 3; i++) {
        const int j = i * 32 + lane;
        if (i == 0) {                              // straddles 29
            const float p = we[j] * s_E[j];
            if (j < EXP_DIM) a0 += p; else a1 += p;
        } else if (i == 1) {                       // straddles 58
            const float p = we[j] * s_E[j];
            if (j < 2 * EXP_DIM) a1 += p; else a2 += p;
        } else {                                   // tail, j < 87
            if (j < EXP3) a2 += we[j] * s_E[j];
        }
    }

    // ---- butterfly reductions: every lane ends with the full sums ----
    #pragma unroll
    for (int off = 16; off > 0; off >>= 1) {
        a0 += __shfl_xor_sync(0xffffffffu, a0, off);
        a1 += __shfl_xor_sync(0xffffffffu, a1, off);
        a2 += __shfl_xor_sync(0xffffffffu, a2, off);
    }

    // ---- parallel epilogue: lane k (k<3) computes output component k ----
    if (lane < 3) {
        const float x = a0 + __ldg(u + 3 * warp + 0);
        const float y = a1 + __ldg(u + 3 * warp + 1);
        const float z = a2 + __ldg(u + 3 * warp + 2);

        const float q0 = __ldg(pose + 4 * lane + 0);
        const float q1 = __ldg(pose + 4 * lane + 1);
        const float q2 = __ldg(pose + 4 * lane + 2);
        const float s  = __ldg(pose + 3) + __ldg(pose + 7) + __ldg(pose + 11);

        const float dot  = q0 * x + q1 * y + q2 * z;
        const float sgn  = (lane == 1) ? -s : s;
        const float add  = (lane == 0) ? __ldg(pose + 3)
                         : (lane == 1) ? (450.0f - __ldg(pose + 7)) : 0.0f;
        const float scl  = (lane == 2) ? 1.0f : (224.0f / 450.0f);

        out[3 * warp + lane] = (sgn * dot + add) * scl;
    }
}

// ---------------------------------------------------------------------------
// Entry point
// Input order: pose_3DMM, alpha_exp, alpha_shp, u_base, w_exp_base, w_shp_base
// ---------------------------------------------------------------------------
extern "C" void kernel_launch(void* const* d_in, const int* in_sizes, int n_in,
                              void* d_out, int out_size)
{
    const float* pose  = (const float*)d_in[0];
    const float* a_exp = (const float*)d_in[1];
    const float* a_shp = (const float*)d_in[2];
    const float* u     = (const float*)d_in[3];
    const float* w_exp = (const float*)d_in[4];
    const float* w_shp = (const float*)d_in[5];
    float* out = (float*)d_out;

    const int blocks = (N_VERTS + WARPS_PER_BLOCK - 1) / WARPS_PER_BLOCK;
    pca_final_kernel<<<blocks, NTHREADS>>>(pose, a_exp, a_shp, u, w_exp, w_shp, out);
}